// round 15
// baseline (speedup 1.0000x reference)
#include <cuda_runtime.h>
#include <cuda_fp16.h>
#include <cstdint>

#define Nn 8192
#define Mm 128
#define EPSf 1e-4f
#define LDA 136                  // fp16 elems per smem tile row (128 + 8 pad)
#define TH 24.0f                 // flag threshold on raw score
#define CAP (4u * 1024u * 1024u) // flagged-entry capacity (32 MB)
#define TLEf (-18.42068074395237f)   // 2*log(1e-4), fp32
#define K2d  (18.420680743952367)    // -2*log(1e-4), fp64

// ---------------- device scratch (allocation-free) ----------------
static __device__ uint2    g_flags[CAP];          // packed (row<<13|col, bits(s))
static __device__ unsigned g_fcount;
static __device__ __half   g_A16[(size_t)Nn * Mm];
static __device__ __half   g_B16[(size_t)Nn * Mm];
static __device__ float    g_Z[Nn];
static __device__ float    g_W[Nn];
static __device__ float    g_rZ[Nn];
static __device__ float    g_rW[Nn];
static __device__ double   g_corr;
static __device__ double   g_lsum;

__device__ __forceinline__ uint32_t smem_u32(const void* p) {
    uint32_t a;
    asm("{ .reg .u64 t; cvta.to.shared.u64 t, %1; cvt.u32.u64 %0, t; }" : "=r"(a) : "l"(p));
    return a;
}
__device__ __forceinline__ void ldmx4(uint32_t* r, uint32_t addr) {
    asm volatile("ldmatrix.sync.aligned.m8n8.x4.shared.b16 {%0,%1,%2,%3}, [%4];"
                 : "=r"(r[0]), "=r"(r[1]), "=r"(r[2]), "=r"(r[3]) : "r"(addr));
}
__device__ __forceinline__ void mma16816h(uint32_t& c0, uint32_t& c1,
                                          const uint32_t* a, uint32_t b0, uint32_t b1) {
    asm volatile(
        "mma.sync.aligned.m16n8k16.row.col.f16.f16.f16.f16 "
        "{%0,%1}, {%2,%3,%4,%5}, {%6,%7}, {%0,%1};"
        : "+r"(c0), "+r"(c1)
        : "r"(a[0]), "r"(a[1]), "r"(a[2]), "r"(a[3]), "r"(b0), "r"(b1));
}

__global__ void prep_kernel(const float* __restrict__ out1, const float* __restrict__ out2) {
    int t = blockIdx.x * blockDim.x + threadIdx.x;
    if (t < Nn * Mm / 4) {
        float4 a = *(const float4*)&out2[(size_t)t * 4];
        float4 b = *(const float4*)&out1[(size_t)t * 4];
        __half2 a0 = __float22half2_rn(make_float2(a.x, a.y));
        __half2 a1 = __float22half2_rn(make_float2(a.z, a.w));
        __half2 b0 = __float22half2_rn(make_float2(b.x, b.y));
        __half2 b1 = __float22half2_rn(make_float2(b.z, b.w));
        *(uint2*)&g_A16[(size_t)t * 4] = make_uint2(*(uint32_t*)&a0, *(uint32_t*)&a1);
        *(uint2*)&g_B16[(size_t)t * 4] = make_uint2(*(uint32_t*)&b0, *(uint32_t*)&b1);
    }
    if (t < Nn) { g_Z[t] = 0.0f; g_W[t] = 0.0f; }
    if (t == 0) { g_corr = 0.0; g_lsum = 0.0; g_fcount = 0u; }
}

#define T_ELEMS (128 * LDA)
#define SMEM_BYTES (2 * T_ELEMS * 2)          // 69632 -> 3 CTAs/SM

__device__ __forceinline__ void load_tiles(__half* At, __half* Bt, int i0, int j0, int tid) {
    #pragma unroll 8
    for (int t = tid; t < 2048; t += 256) {
        int row = t >> 4, q = (t & 15) * 8;
        *(uint4*)&At[row * LDA + q] = *(const uint4*)&g_A16[(size_t)(i0 + row) * Mm + q];
        *(uint4*)&Bt[row * LDA + q] = *(const uint4*)&g_B16[(size_t)(j0 + row) * Mm + q];
    }
}

// MMA body, warp tile 32(m) x 64(n), fp16 accum: ch[2][8][2]
__device__ __forceinline__ void mma_tile_h(uint32_t sA, uint32_t sB, int m0w, int n0w,
                                           int lane, uint32_t ch[2][8][2]) {
    const int aro = (lane & 7) + ((lane >> 3) & 1) * 8;
    const int ako = ((lane >> 4) & 1) * 8;
    const int bro = (lane & 7) + ((lane >> 4) & 1) * 8;
    const int bko = ((lane >> 3) & 1) * 8;
    const uint32_t aoff = (uint32_t)(((m0w + aro) * LDA + ako) * 2);
    uint32_t boff[4];
    #pragma unroll
    for (int p = 0; p < 4; p++)
        boff[p] = (uint32_t)(((n0w + p * 16 + bro) * LDA + bko) * 2);

    #pragma unroll
    for (int kk = 0; kk < 8; kk++) {
        const uint32_t kb = (uint32_t)(kk * 32);
        uint32_t av[2][4], bv[4][4];
        #pragma unroll
        for (int mt = 0; mt < 2; mt++)
            ldmx4(av[mt], sA + aoff + (uint32_t)(mt * 16 * LDA * 2) + kb);
        #pragma unroll
        for (int p = 0; p < 4; p++)
            ldmx4(bv[p], sB + boff[p] + kb);
        #pragma unroll
        for (int mt = 0; mt < 2; mt++)
            #pragma unroll
            for (int nt = 0; nt < 8; nt++) {
                const int p = nt >> 1, r = (nt & 1) * 2;
                mma16816h(ch[mt][nt][0], ch[mt][nt][1], av[mt], bv[p][r], bv[p][r + 1]);
            }
    }
}

// ---- Pass 1: GEMM -> Z/W sums + label-tile sum + flagged compaction ----
__global__ __launch_bounds__(256, 3) void pass1_sums(const float* __restrict__ label) {
    extern __shared__ char sm[];
    __half* At = (__half*)sm;
    __half* Bt = At + T_ELEMS;

    const int tid = threadIdx.x, wid = tid >> 5, lane = tid & 31;
    const int i0 = blockIdx.y * 128, j0 = blockIdx.x * 128;
    const int m0w = (wid & 3) * 32, n0w = (wid >> 2) * 64;

    load_tiles(At, Bt, i0, j0, tid);
    __syncthreads();

    uint32_t ch[2][8][2] = {};
    mma_tile_h(smem_u32(At), smem_u32(Bt), m0w, n0w, lane, ch);

    // label tile sum: 128 x 128 f32, coalesced; streams on the idle DRAM pipe
    float lsum = 0.f;
    #pragma unroll 4
    for (int t = tid; t < 4096; t += 256) {
        int row = t >> 5, cx = (t & 31) * 4;
        float4 v = *(const float4*)&label[(size_t)(i0 + row) * Nn + j0 + cx];
        lsum += (v.x + v.y) + (v.z + v.w);
    }

    // exp + Z/W sums from fragments
    float rs[2][2] = {{0.f, 0.f}, {0.f, 0.f}};
    const int rq = lane >> 2;
    #pragma unroll
    for (int nt = 0; nt < 8; nt++) {
        float2 f00 = __half22float2(*(__half2*)&ch[0][nt][0]);
        float2 f01 = __half22float2(*(__half2*)&ch[0][nt][1]);
        float2 f10 = __half22float2(*(__half2*)&ch[1][nt][0]);
        float2 f11 = __half22float2(*(__half2*)&ch[1][nt][1]);

        float e00x = __expf(f00.x), e00y = __expf(f00.y);
        float e01x = __expf(f01.x), e01y = __expf(f01.y);
        float e10x = __expf(f10.x), e10y = __expf(f10.y);
        float e11x = __expf(f11.x), e11y = __expf(f11.y);

        rs[0][0] += e00x + e00y;  rs[0][1] += e01x + e01y;
        rs[1][0] += e10x + e10y;  rs[1][1] += e11x + e11y;

        float v0 = e00x + e01x + e10x + e11x;
        float v1 = e00y + e01y + e10y + e11y;
        v0 += __shfl_xor_sync(0xFFFFFFFF, v0, 4);
        v0 += __shfl_xor_sync(0xFFFFFFFF, v0, 8);
        v0 += __shfl_xor_sync(0xFFFFFFFF, v0, 16);
        v1 += __shfl_xor_sync(0xFFFFFFFF, v1, 4);
        v1 += __shfl_xor_sync(0xFFFFFFFF, v1, 8);
        v1 += __shfl_xor_sync(0xFFFFFFFF, v1, 16);
        if (lane < 4) {
            int col2 = j0 + n0w + nt * 8 + lane * 2;
            atomicAdd(&g_W[col2], v0);
            atomicAdd(&g_W[col2 + 1], v1);
        }
    }
    #pragma unroll
    for (int mt = 0; mt < 2; mt++) {
        float r0 = rs[mt][0], r1 = rs[mt][1];
        r0 += __shfl_xor_sync(0xFFFFFFFF, r0, 1);
        r0 += __shfl_xor_sync(0xFFFFFFFF, r0, 2);
        r1 += __shfl_xor_sync(0xFFFFFFFF, r1, 1);
        r1 += __shfl_xor_sync(0xFFFFFFFF, r1, 2);
        if ((lane & 3) == 0) {
            atomicAdd(&g_Z[i0 + m0w + mt * 16 + rq], r0);
            atomicAdd(&g_Z[i0 + m0w + mt * 16 + 8 + rq], r1);
        }
    }

    // flag count (per thread) then warp reduce lsum + count
    int fcnt = 0;
    #pragma unroll
    for (int mt = 0; mt < 2; mt++)
        #pragma unroll
        for (int nt = 0; nt < 8; nt++)
            #pragma unroll
            for (int h = 0; h < 2; h++) {
                float2 f = __half22float2(*(__half2*)&ch[mt][nt][h]);
                fcnt += (f.x > TH) + (f.y > TH);
            }
    #pragma unroll
    for (int o = 16; o; o >>= 1) {
        lsum += __shfl_xor_sync(0xFFFFFFFF, lsum, o);
        fcnt += __shfl_xor_sync(0xFFFFFFFF, fcnt, o);
    }

    __syncthreads();                       // all tile reads complete; reuse smem
    float*    sL = (float*)sm;             // [8]
    int*      sC = (int*)(sm + 32);        // [8]
    unsigned* sBase = (unsigned*)(sm + 64);
    if (lane == 0) { sL[wid] = lsum; sC[wid] = fcnt; }
    __syncthreads();
    if (tid == 0) {
        float Ls = 0.f; int tot = 0;
        #pragma unroll
        for (int w = 0; w < 8; w++) { Ls += sL[w]; tot += sC[w]; }
        atomicAdd(&g_lsum, (double)Ls);
        *sBase = atomicAdd(&g_fcount, (unsigned)tot);
    }
    __syncthreads();
    unsigned off = *sBase;
    for (int w = 0; w < wid; w++) off += (unsigned)sC[w];

    // ballot-compacted flag write
    const unsigned ltm = (1u << lane) - 1u;
    #pragma unroll
    for (int mt = 0; mt < 2; mt++)
        #pragma unroll
        for (int nt = 0; nt < 8; nt++)
            #pragma unroll
            for (int h = 0; h < 2; h++) {
                float2 f = __half22float2(*(__half2*)&ch[mt][nt][h]);
                unsigned row = (unsigned)(i0 + m0w + mt * 16 + h * 8 + rq);
                unsigned col = (unsigned)(j0 + n0w + nt * 8 + (lane & 3) * 2);
                unsigned mx = __ballot_sync(0xFFFFFFFF, f.x > TH);
                if (f.x > TH) {
                    unsigned p = off + __popc(mx & ltm);
                    if (p < CAP) g_flags[p] = make_uint2((row << 13) | col, __float_as_uint(f.x));
                }
                off += __popc(mx);
                unsigned my = __ballot_sync(0xFFFFFFFF, f.y > TH);
                if (f.y > TH) {
                    unsigned p = off + __popc(my & ltm);
                    if (p < CAP) g_flags[p] = make_uint2((row << 13) | (col + 1), __float_as_uint(f.y));
                }
                off += __popc(my);
            }
}

__global__ void recip_kernel() {
    int i = blockIdx.x * blockDim.x + threadIdx.x;
    if (i < Nn) { g_rZ[i] = 1.0f / g_Z[i]; g_rW[i] = 1.0f / g_W[i]; }
}

// ---- Pass 3: sparse corrections on flagged entries ----
__global__ __launch_bounds__(256) void pass3_corr(const float* __restrict__ label) {
    unsigned n = g_fcount; if (n > CAP) n = CAP;
    unsigned idx = blockIdx.x * 256u + threadIdx.x;
    if (blockIdx.x * 256u >= n) return;    // uniform early exit for empty blocks

    __shared__ float sred[256];
    float v = 0.f;
    if (idx < n) {
        uint2 e = g_flags[idx];
        int i = (int)(e.x >> 13), j = (int)(e.x & 8191u);
        float s  = __uint_as_float(e.y);
        float es = __expf(s);
        float x  = fmaf(es, g_rZ[i], EPSf) * fmaf(es, g_rW[j], EPSf);
        v = label[(size_t)i * Nn + j] * (__logf(x) - TLEf);
    }
    sred[threadIdx.x] = v;
    __syncthreads();
    #pragma unroll
    for (int s = 128; s > 0; s >>= 1) {
        if (threadIdx.x < (unsigned)s) sred[threadIdx.x] += sred[threadIdx.x + s];
        __syncthreads();
    }
    if (threadIdx.x == 0) atomicAdd(&g_corr, (double)sred[0]);
}

__global__ void final_kernel(float* out) {
    out[0] = (float)(K2d * g_lsum - g_corr);
}

extern "C" void kernel_launch(void* const* d_in, const int* in_sizes, int n_in,
                              void* d_out, int out_size) {
    const float* out1  = (const float*)d_in[0];
    const float* out2  = (const float*)d_in[1];
    const float* label = (const float*)d_in[2];

    cudaFuncSetAttribute(pass1_sums, cudaFuncAttributeMaxDynamicSharedMemorySize, SMEM_BYTES);

    prep_kernel<<<(Nn * Mm / 4 + 255) / 256, 256>>>(out1, out2);
    dim3 grid(Nn / 128, Nn / 128);
    pass1_sums<<<grid, 256, SMEM_BYTES>>>(label);
    recip_kernel<<<32, 256>>>();
    pass3_corr<<<CAP / 256, 256>>>(label);
    final_kernel<<<1, 1>>>((float*)d_out);
}

// round 16
// speedup vs baseline: 1.1621x; 1.1621x over previous
#include <cuda_runtime.h>
#include <cuda_fp16.h>
#include <cstdint>

#define Nn 8192
#define Mm 128
#define EPSf 1e-4f
#define LDA 136                  // fp16 elems per smem tile row (128 + 8 pad)
#define TH 24.0f                 // flag threshold on raw score
#define CAP (4u * 1024u * 1024u) // global flagged-entry capacity
#define SCAP 4096                // per-CTA smem flag capacity
#define TLEf (-18.42068074395237f)   // 2*log(1e-4)
#define K2d  (18.420680743952367)    // -2*log(1e-4)

// ---------------- device scratch (allocation-free) ----------------
static __device__ uint2    g_flags[CAP];
static __device__ unsigned g_fcount;
static __device__ __half   g_A16[(size_t)Nn * Mm];
static __device__ __half   g_B16[(size_t)Nn * Mm];
static __device__ float    g_Z[Nn];
static __device__ float    g_W[Nn];
static __device__ float    g_rZ[Nn];
static __device__ float    g_rW[Nn];
static __device__ double   g_corr;
static __device__ double   g_lsum;

__device__ __forceinline__ uint32_t smem_u32(const void* p) {
    uint32_t a;
    asm("{ .reg .u64 t; cvta.to.shared.u64 t, %1; cvt.u32.u64 %0, t; }" : "=r"(a) : "l"(p));
    return a;
}
__device__ __forceinline__ void ldmx4(uint32_t* r, uint32_t addr) {
    asm volatile("ldmatrix.sync.aligned.m8n8.x4.shared.b16 {%0,%1,%2,%3}, [%4];"
                 : "=r"(r[0]), "=r"(r[1]), "=r"(r[2]), "=r"(r[3]) : "r"(addr));
}
__device__ __forceinline__ void mma16816h(uint32_t& c0, uint32_t& c1,
                                          const uint32_t* a, uint32_t b0, uint32_t b1) {
    asm volatile(
        "mma.sync.aligned.m16n8k16.row.col.f16.f16.f16.f16 "
        "{%0,%1}, {%2,%3,%4,%5}, {%6,%7}, {%0,%1};"
        : "+r"(c0), "+r"(c1)
        : "r"(a[0]), "r"(a[1]), "r"(a[2]), "r"(a[3]), "r"(b0), "r"(b1));
}

__global__ void prep_kernel(const float* __restrict__ out1, const float* __restrict__ out2) {
    int t = blockIdx.x * blockDim.x + threadIdx.x;
    if (t < Nn * Mm / 4) {
        float4 a = *(const float4*)&out2[(size_t)t * 4];
        float4 b = *(const float4*)&out1[(size_t)t * 4];
        __half2 a0 = __float22half2_rn(make_float2(a.x, a.y));
        __half2 a1 = __float22half2_rn(make_float2(a.z, a.w));
        __half2 b0 = __float22half2_rn(make_float2(b.x, b.y));
        __half2 b1 = __float22half2_rn(make_float2(b.z, b.w));
        *(uint2*)&g_A16[(size_t)t * 4] = make_uint2(*(uint32_t*)&a0, *(uint32_t*)&a1);
        *(uint2*)&g_B16[(size_t)t * 4] = make_uint2(*(uint32_t*)&b0, *(uint32_t*)&b1);
    }
    if (t < Nn) { g_Z[t] = 0.0f; g_W[t] = 0.0f; }
    if (t == 0) { g_corr = 0.0; g_lsum = 0.0; g_fcount = 0u; }
}

#define T_ELEMS (128 * LDA)
#define SMEM_BYTES (2 * T_ELEMS * 2)          // 69632 -> 3 CTAs/SM

__device__ __forceinline__ void load_tiles(__half* At, __half* Bt, int i0, int j0, int tid) {
    #pragma unroll 8
    for (int t = tid; t < 2048; t += 256) {
        int row = t >> 4, q = (t & 15) * 8;
        *(uint4*)&At[row * LDA + q] = *(const uint4*)&g_A16[(size_t)(i0 + row) * Mm + q];
        *(uint4*)&Bt[row * LDA + q] = *(const uint4*)&g_B16[(size_t)(j0 + row) * Mm + q];
    }
}

__device__ __forceinline__ void mma_tile_h(uint32_t sA, uint32_t sB, int m0w, int n0w,
                                           int lane, uint32_t ch[2][8][2]) {
    const int aro = (lane & 7) + ((lane >> 3) & 1) * 8;
    const int ako = ((lane >> 4) & 1) * 8;
    const int bro = (lane & 7) + ((lane >> 4) & 1) * 8;
    const int bko = ((lane >> 3) & 1) * 8;
    const uint32_t aoff = (uint32_t)(((m0w + aro) * LDA + ako) * 2);
    uint32_t boff[4];
    #pragma unroll
    for (int p = 0; p < 4; p++)
        boff[p] = (uint32_t)(((n0w + p * 16 + bro) * LDA + bko) * 2);

    #pragma unroll
    for (int kk = 0; kk < 8; kk++) {
        const uint32_t kb = (uint32_t)(kk * 32);
        uint32_t av[2][4], bv[4][4];
        #pragma unroll
        for (int mt = 0; mt < 2; mt++)
            ldmx4(av[mt], sA + aoff + (uint32_t)(mt * 16 * LDA * 2) + kb);
        #pragma unroll
        for (int p = 0; p < 4; p++)
            ldmx4(bv[p], sB + boff[p] + kb);
        #pragma unroll
        for (int mt = 0; mt < 2; mt++)
            #pragma unroll
            for (int nt = 0; nt < 8; nt++) {
                const int p = nt >> 1, r = (nt & 1) * 2;
                mma16816h(ch[mt][nt][0], ch[mt][nt][1], av[mt], bv[p][r], bv[p][r + 1]);
            }
    }
}

// ---- Pass 1: GEMM -> Z/W sums + smem flag append -> flag dump -> label sum ----
__global__ __launch_bounds__(256, 3) void pass1_sums(const float* __restrict__ label) {
    extern __shared__ char sm[];
    __half* At = (__half*)sm;
    __half* Bt = At + T_ELEMS;
    uint2*    sFlag = (uint2*)sm;                        // overlays tiles (32 KB)
    unsigned* sCnt  = (unsigned*)(sm + SCAP * 8);
    unsigned* sBase = (unsigned*)(sm + SCAP * 8 + 4);
    float*    sL    = (float*)(sm + SCAP * 8 + 8);       // [8]

    const int tid = threadIdx.x, wid = tid >> 5, lane = tid & 31;
    const int i0 = blockIdx.y * 128, j0 = blockIdx.x * 128;
    const int m0w = (wid & 3) * 32, n0w = (wid >> 2) * 64;

    load_tiles(At, Bt, i0, j0, tid);
    __syncthreads();

    uint32_t ch[2][8][2] = {};
    mma_tile_h(smem_u32(At), smem_u32(Bt), m0w, n0w, lane, ch);

    __syncthreads();                 // tiles dead; flag region usable
    if (tid == 0) *sCnt = 0u;
    __syncthreads();

    // fragment loop: exp + Z/W sums + flag append (ch live, R14-level pressure)
    float rs[2][2] = {{0.f, 0.f}, {0.f, 0.f}};
    const int rq = lane >> 2;
    const int cq = (lane & 3) * 2;
    #pragma unroll
    for (int nt = 0; nt < 8; nt++) {
        float2 f00 = __half22float2(*(__half2*)&ch[0][nt][0]);
        float2 f01 = __half22float2(*(__half2*)&ch[0][nt][1]);
        float2 f10 = __half22float2(*(__half2*)&ch[1][nt][0]);
        float2 f11 = __half22float2(*(__half2*)&ch[1][nt][1]);

        // flag appends (rare: ~1.7 % of entries)
        const unsigned colg = (unsigned)(j0 + n0w + nt * 8 + cq);
        #pragma unroll
        for (int h = 0; h < 4; h++) {
            float2 f = (h == 0) ? f00 : (h == 1) ? f01 : (h == 2) ? f10 : f11;
            unsigned rowg = (unsigned)(i0 + m0w + ((h >> 1) ? 16 : 0) + ((h & 1) ? 8 : 0) + rq);
            if (f.x > TH) {
                unsigned p = atomicAdd(sCnt, 1u);
                if (p < SCAP) sFlag[p] = make_uint2((rowg << 13) | colg, __float_as_uint(f.x));
            }
            if (f.y > TH) {
                unsigned p = atomicAdd(sCnt, 1u);
                if (p < SCAP) sFlag[p] = make_uint2((rowg << 13) | (colg + 1), __float_as_uint(f.y));
            }
        }

        float e00x = __expf(f00.x), e00y = __expf(f00.y);
        float e01x = __expf(f01.x), e01y = __expf(f01.y);
        float e10x = __expf(f10.x), e10y = __expf(f10.y);
        float e11x = __expf(f11.x), e11y = __expf(f11.y);

        rs[0][0] += e00x + e00y;  rs[0][1] += e01x + e01y;
        rs[1][0] += e10x + e10y;  rs[1][1] += e11x + e11y;

        float v0 = e00x + e01x + e10x + e11x;
        float v1 = e00y + e01y + e10y + e11y;
        v0 += __shfl_xor_sync(0xFFFFFFFF, v0, 4);
        v0 += __shfl_xor_sync(0xFFFFFFFF, v0, 8);
        v0 += __shfl_xor_sync(0xFFFFFFFF, v0, 16);
        v1 += __shfl_xor_sync(0xFFFFFFFF, v1, 4);
        v1 += __shfl_xor_sync(0xFFFFFFFF, v1, 8);
        v1 += __shfl_xor_sync(0xFFFFFFFF, v1, 16);
        if (lane < 4) {
            int col2 = j0 + n0w + nt * 8 + lane * 2;
            atomicAdd(&g_W[col2], v0);
            atomicAdd(&g_W[col2 + 1], v1);
        }
    }
    #pragma unroll
    for (int mt = 0; mt < 2; mt++) {
        float r0 = rs[mt][0], r1 = rs[mt][1];
        r0 += __shfl_xor_sync(0xFFFFFFFF, r0, 1);
        r0 += __shfl_xor_sync(0xFFFFFFFF, r0, 2);
        r1 += __shfl_xor_sync(0xFFFFFFFF, r1, 1);
        r1 += __shfl_xor_sync(0xFFFFFFFF, r1, 2);
        if ((lane & 3) == 0) {
            atomicAdd(&g_Z[i0 + m0w + mt * 16 + rq], r0);
            atomicAdd(&g_Z[i0 + m0w + mt * 16 + 8 + rq], r1);
        }
    }
    __syncthreads();                 // sCnt final; ch dead below

    unsigned cnt = *sCnt; if (cnt > SCAP) cnt = SCAP;
    if (tid == 0) *sBase = atomicAdd(&g_fcount, cnt);
    __syncthreads();
    const unsigned base = *sBase;
    for (unsigned t = tid; t < cnt; t += 256)
        if (base + t < CAP) g_flags[base + t] = sFlag[t];

    // label tile sum (registers free now; DRAM pipe otherwise idle)
    float lsum = 0.f;
    #pragma unroll 4
    for (int t = tid; t < 4096; t += 256) {
        int row = t >> 5, cx = (t & 31) * 4;
        float4 v = *(const float4*)&label[(size_t)(i0 + row) * Nn + j0 + cx];
        lsum += (v.x + v.y) + (v.z + v.w);
    }
    #pragma unroll
    for (int o = 16; o; o >>= 1)
        lsum += __shfl_xor_sync(0xFFFFFFFF, lsum, o);
    if (lane == 0) sL[wid] = lsum;
    __syncthreads();
    if (tid == 0) {
        float Ls = 0.f;
        #pragma unroll
        for (int w = 0; w < 8; w++) Ls += sL[w];
        atomicAdd(&g_lsum, (double)Ls);
    }
}

__global__ void recip_kernel() {
    int i = blockIdx.x * blockDim.x + threadIdx.x;
    if (i < Nn) { g_rZ[i] = 1.0f / g_Z[i]; g_rW[i] = 1.0f / g_W[i]; }
}

// ---- Pass 3: sparse corrections, grid-stride with ILP ----
__global__ __launch_bounds__(256) void pass3_corr(const float* __restrict__ label) {
    unsigned n = g_fcount; if (n > CAP) n = CAP;
    const unsigned stride = gridDim.x * 256u;
    float acc = 0.f;
    for (unsigned idx = blockIdx.x * 256u + threadIdx.x; idx < n; idx += stride) {
        uint2 e = g_flags[idx];
        int i = (int)(e.x >> 13), j = (int)(e.x & 8191u);
        float s  = __uint_as_float(e.y);
        float es = __expf(s);
        float x  = fmaf(es, g_rZ[i], EPSf) * fmaf(es, g_rW[j], EPSf);
        acc += label[(size_t)i * Nn + j] * (__logf(x) - TLEf);
    }
    __shared__ float sred[256];
    sred[threadIdx.x] = acc;
    __syncthreads();
    #pragma unroll
    for (int s = 128; s > 0; s >>= 1) {
        if (threadIdx.x < (unsigned)s) sred[threadIdx.x] += sred[threadIdx.x + s];
        __syncthreads();
    }
    if (threadIdx.x == 0 && sred[0] != 0.f) atomicAdd(&g_corr, (double)sred[0]);
}

__global__ void final_kernel(float* out) {
    out[0] = (float)(K2d * g_lsum - g_corr);
}

extern "C" void kernel_launch(void* const* d_in, const int* in_sizes, int n_in,
                              void* d_out, int out_size) {
    const float* out1  = (const float*)d_in[0];
    const float* out2  = (const float*)d_in[1];
    const float* label = (const float*)d_in[2];

    cudaFuncSetAttribute(pass1_sums, cudaFuncAttributeMaxDynamicSharedMemorySize, SMEM_BYTES);

    prep_kernel<<<(Nn * Mm / 4 + 255) / 256, 256>>>(out1, out2);
    dim3 grid(Nn / 128, Nn / 128);
    pass1_sums<<<grid, 256, SMEM_BYTES>>>(label);
    recip_kernel<<<32, 256>>>();
    pass3_corr<<<1024, 256>>>(label);
    final_kernel<<<1, 1>>>((float*)d_out);
}

// round 17
// speedup vs baseline: 1.2935x; 1.1131x over previous
#include <cuda_runtime.h>
#include <cuda_fp16.h>
#include <cstdint>

#define Nn 8192
#define Mm 128
#define EPSf 1e-4f
#define LDA 136                  // fp16 elems per smem tile row (128 + 8 pad)
#define TH 28.0f                 // flag threshold on raw score
#define CAP (4u * 1024u * 1024u)
#define SCAP 2048                // per-CTA smem flag capacity
#define TLEf (-18.42068074395237f)   // 2*log(1e-4)
#define K2d  (18.420680743952367)    // -2*log(1e-4)

// ---------------- device scratch (allocation-free) ----------------
static __device__ uint2    g_flags[CAP];
static __device__ unsigned g_fcount;
static __device__ __half   g_A16[(size_t)Nn * Mm];
static __device__ __half   g_B16[(size_t)Nn * Mm];
static __device__ float    g_Z[Nn];
static __device__ float    g_W[Nn];
static __device__ float    g_rZ[Nn];
static __device__ float    g_rW[Nn];
static __device__ double   g_corr;
static __device__ double   g_lsum;

__device__ __forceinline__ uint32_t smem_u32(const void* p) {
    uint32_t a;
    asm("{ .reg .u64 t; cvta.to.shared.u64 t, %1; cvt.u32.u64 %0, t; }" : "=r"(a) : "l"(p));
    return a;
}
__device__ __forceinline__ void ldmx4(uint32_t* r, uint32_t addr) {
    asm volatile("ldmatrix.sync.aligned.m8n8.x4.shared.b16 {%0,%1,%2,%3}, [%4];"
                 : "=r"(r[0]), "=r"(r[1]), "=r"(r[2]), "=r"(r[3]) : "r"(addr));
}
__device__ __forceinline__ void mma16816h(uint32_t& c0, uint32_t& c1,
                                          const uint32_t* a, uint32_t b0, uint32_t b1) {
    asm volatile(
        "mma.sync.aligned.m16n8k16.row.col.f16.f16.f16.f16 "
        "{%0,%1}, {%2,%3,%4,%5}, {%6,%7}, {%0,%1};"
        : "+r"(c0), "+r"(c1)
        : "r"(a[0]), "r"(a[1]), "r"(a[2]), "r"(a[3]), "r"(b0), "r"(b1));
}

__global__ void prep_kernel(const float* __restrict__ out1, const float* __restrict__ out2) {
    int t = blockIdx.x * blockDim.x + threadIdx.x;
    if (t < Nn * Mm / 4) {
        float4 a = *(const float4*)&out2[(size_t)t * 4];
        float4 b = *(const float4*)&out1[(size_t)t * 4];
        __half2 a0 = __float22half2_rn(make_float2(a.x, a.y));
        __half2 a1 = __float22half2_rn(make_float2(a.z, a.w));
        __half2 b0 = __float22half2_rn(make_float2(b.x, b.y));
        __half2 b1 = __float22half2_rn(make_float2(b.z, b.w));
        *(uint2*)&g_A16[(size_t)t * 4] = make_uint2(*(uint32_t*)&a0, *(uint32_t*)&a1);
        *(uint2*)&g_B16[(size_t)t * 4] = make_uint2(*(uint32_t*)&b0, *(uint32_t*)&b1);
    }
    if (t < Nn) { g_Z[t] = 0.0f; g_W[t] = 0.0f; }
    if (t == 0) { g_corr = 0.0; g_lsum = 0.0; g_fcount = 0u; }
}

#define T_ELEMS (128 * LDA)
#define SMEM_BYTES (2 * T_ELEMS * 2)          // 69632 -> 3 CTAs/SM

__device__ __forceinline__ void load_tiles(__half* At, __half* Bt, int i0, int j0, int tid) {
    #pragma unroll 8
    for (int t = tid; t < 2048; t += 256) {
        int row = t >> 4, q = (t & 15) * 8;
        *(uint4*)&At[row * LDA + q] = *(const uint4*)&g_A16[(size_t)(i0 + row) * Mm + q];
        *(uint4*)&Bt[row * LDA + q] = *(const uint4*)&g_B16[(size_t)(j0 + row) * Mm + q];
    }
}

__device__ __forceinline__ void mma_tile_h(uint32_t sA, uint32_t sB, int m0w, int n0w,
                                           int lane, uint32_t ch[2][8][2]) {
    const int aro = (lane & 7) + ((lane >> 3) & 1) * 8;
    const int ako = ((lane >> 4) & 1) * 8;
    const int bro = (lane & 7) + ((lane >> 4) & 1) * 8;
    const int bko = ((lane >> 3) & 1) * 8;
    const uint32_t aoff = (uint32_t)(((m0w + aro) * LDA + ako) * 2);
    uint32_t boff[4];
    #pragma unroll
    for (int p = 0; p < 4; p++)
        boff[p] = (uint32_t)(((n0w + p * 16 + bro) * LDA + bko) * 2);

    #pragma unroll
    for (int kk = 0; kk < 8; kk++) {
        const uint32_t kb = (uint32_t)(kk * 32);
        uint32_t av[2][4], bv[4][4];
        #pragma unroll
        for (int mt = 0; mt < 2; mt++)
            ldmx4(av[mt], sA + aoff + (uint32_t)(mt * 16 * LDA * 2) + kb);
        #pragma unroll
        for (int p = 0; p < 4; p++)
            ldmx4(bv[p], sB + boff[p] + kb);
        #pragma unroll
        for (int mt = 0; mt < 2; mt++)
            #pragma unroll
            for (int nt = 0; nt < 8; nt++) {
                const int p = nt >> 1, r = (nt & 1) * 2;
                mma16816h(ch[mt][nt][0], ch[mt][nt][1], av[mt], bv[p][r], bv[p][r + 1]);
            }
    }
}

// ---- Fused pass: 4096 tensor CTAs + 512 label-streamer CTAs in one grid ----
__global__ __launch_bounds__(256, 3) void fused_pass(const float* __restrict__ label) {
    extern __shared__ char sm[];
    const int tid = threadIdx.x, wid = tid >> 5, lane = tid & 31;
    const int bx = blockIdx.x;
    const int r9 = bx % 9;

    if (r9 == 8) {
        // ---------- streamer role: sum 16 label rows (512 KB), coalesced ----------
        const int sid = bx / 9;                          // 0..511
        const float4* b4 = (const float4*)(label + (size_t)sid * 16 * Nn);
        float ls = 0.f;
        #pragma unroll 4
        for (int t = tid; t < 32768; t += 256) {
            float4 v = b4[t];
            ls += (v.x + v.y) + (v.z + v.w);
        }
        #pragma unroll
        for (int o = 16; o; o >>= 1)
            ls += __shfl_xor_sync(0xFFFFFFFF, ls, o);
        float* sL = (float*)sm;
        if (lane == 0) sL[wid] = ls;
        __syncthreads();
        if (tid == 0) {
            float s = 0.f;
            #pragma unroll
            for (int w = 0; w < 8; w++) s += sL[w];
            atomicAdd(&g_lsum, (double)s);
        }
        return;
    }

    // ---------- tensor role ----------
    const int tix = (bx / 9) * 8 + r9;                   // 0..4095
    const int i0 = (tix >> 6) * 128, j0 = (tix & 63) * 128;

    __half* At = (__half*)sm;
    __half* Bt = At + T_ELEMS;
    uint2*    sFlag = (uint2*)sm;                        // overlays tiles after MMA
    unsigned* sCnt  = (unsigned*)(sm + SCAP * 8);
    unsigned* sBase = (unsigned*)(sm + SCAP * 8 + 4);

    const int m0w = (wid & 3) * 32, n0w = (wid >> 2) * 64;

    load_tiles(At, Bt, i0, j0, tid);
    __syncthreads();

    uint32_t ch[2][8][2] = {};
    mma_tile_h(smem_u32(At), smem_u32(Bt), m0w, n0w, lane, ch);

    __syncthreads();                 // tiles dead; flag region usable
    if (tid == 0) *sCnt = 0u;
    __syncthreads();

    float rs[2][2] = {{0.f, 0.f}, {0.f, 0.f}};
    const int rq = lane >> 2;
    const int cq = (lane & 3) * 2;
    #pragma unroll
    for (int nt = 0; nt < 8; nt++) {
        float2 f00 = __half22float2(*(__half2*)&ch[0][nt][0]);
        float2 f01 = __half22float2(*(__half2*)&ch[0][nt][1]);
        float2 f10 = __half22float2(*(__half2*)&ch[1][nt][0]);
        float2 f11 = __half22float2(*(__half2*)&ch[1][nt][1]);

        const unsigned colg = (unsigned)(j0 + n0w + nt * 8 + cq);
        #pragma unroll
        for (int h = 0; h < 4; h++) {
            float2 f = (h == 0) ? f00 : (h == 1) ? f01 : (h == 2) ? f10 : f11;
            unsigned rowg = (unsigned)(i0 + m0w + ((h >> 1) ? 16 : 0) + ((h & 1) ? 8 : 0) + rq);
            if (f.x > TH) {
                unsigned p = atomicAdd(sCnt, 1u);
                if (p < SCAP) sFlag[p] = make_uint2((rowg << 13) | colg, __float_as_uint(f.x));
            }
            if (f.y > TH) {
                unsigned p = atomicAdd(sCnt, 1u);
                if (p < SCAP) sFlag[p] = make_uint2((rowg << 13) | (colg + 1), __float_as_uint(f.y));
            }
        }

        float e00x = __expf(f00.x), e00y = __expf(f00.y);
        float e01x = __expf(f01.x), e01y = __expf(f01.y);
        float e10x = __expf(f10.x), e10y = __expf(f10.y);
        float e11x = __expf(f11.x), e11y = __expf(f11.y);

        rs[0][0] += e00x + e00y;  rs[0][1] += e01x + e01y;
        rs[1][0] += e10x + e10y;  rs[1][1] += e11x + e11y;

        float v0 = e00x + e01x + e10x + e11x;
        float v1 = e00y + e01y + e10y + e11y;
        v0 += __shfl_xor_sync(0xFFFFFFFF, v0, 4);
        v0 += __shfl_xor_sync(0xFFFFFFFF, v0, 8);
        v0 += __shfl_xor_sync(0xFFFFFFFF, v0, 16);
        v1 += __shfl_xor_sync(0xFFFFFFFF, v1, 4);
        v1 += __shfl_xor_sync(0xFFFFFFFF, v1, 8);
        v1 += __shfl_xor_sync(0xFFFFFFFF, v1, 16);
        if (lane < 4) {
            int col2 = j0 + n0w + nt * 8 + lane * 2;
            atomicAdd(&g_W[col2], v0);
            atomicAdd(&g_W[col2 + 1], v1);
        }
    }
    #pragma unroll
    for (int mt = 0; mt < 2; mt++) {
        float r0 = rs[mt][0], r1 = rs[mt][1];
        r0 += __shfl_xor_sync(0xFFFFFFFF, r0, 1);
        r0 += __shfl_xor_sync(0xFFFFFFFF, r0, 2);
        r1 += __shfl_xor_sync(0xFFFFFFFF, r1, 1);
        r1 += __shfl_xor_sync(0xFFFFFFFF, r1, 2);
        if ((lane & 3) == 0) {
            atomicAdd(&g_Z[i0 + m0w + mt * 16 + rq], r0);
            atomicAdd(&g_Z[i0 + m0w + mt * 16 + 8 + rq], r1);
        }
    }
    __syncthreads();

    unsigned cnt = *sCnt; if (cnt > SCAP) cnt = SCAP;
    if (tid == 0) *sBase = atomicAdd(&g_fcount, cnt);
    __syncthreads();
    const unsigned base = *sBase;
    for (unsigned t = tid; t < cnt; t += 256)
        if (base + t < CAP) g_flags[base + t] = sFlag[t];
}

__global__ void recip_kernel() {
    int i = blockIdx.x * blockDim.x + threadIdx.x;
    if (i < Nn) { g_rZ[i] = 1.0f / g_Z[i]; g_rW[i] = 1.0f / g_W[i]; }
}

// ---- Pass 3: sparse corrections ----
__global__ __launch_bounds__(256) void pass3_corr(const float* __restrict__ label) {
    unsigned n = g_fcount; if (n > CAP) n = CAP;
    const unsigned stride = gridDim.x * 256u;
    float acc = 0.f;
    for (unsigned idx = blockIdx.x * 256u + threadIdx.x; idx < n; idx += stride) {
        uint2 e = g_flags[idx];
        int i = (int)(e.x >> 13), j = (int)(e.x & 8191u);
        float s  = __uint_as_float(e.y);
        float es = __expf(s);
        float x  = fmaf(es, g_rZ[i], EPSf) * fmaf(es, g_rW[j], EPSf);
        acc += label[(size_t)i * Nn + j] * (__logf(x) - TLEf);
    }
    __shared__ float sred[256];
    sred[threadIdx.x] = acc;
    __syncthreads();
    #pragma unroll
    for (int s = 128; s > 0; s >>= 1) {
        if (threadIdx.x < (unsigned)s) sred[threadIdx.x] += sred[threadIdx.x + s];
        __syncthreads();
    }
    if (threadIdx.x == 0 && sred[0] != 0.f) atomicAdd(&g_corr, (double)sred[0]);
}

__global__ void final_kernel(float* out) {
    out[0] = (float)(K2d * g_lsum - g_corr);
}

extern "C" void kernel_launch(void* const* d_in, const int* in_sizes, int n_in,
                              void* d_out, int out_size) {
    const float* out1  = (const float*)d_in[0];
    const float* out2  = (const float*)d_in[1];
    const float* label = (const float*)d_in[2];

    cudaFuncSetAttribute(fused_pass, cudaFuncAttributeMaxDynamicSharedMemorySize, SMEM_BYTES);

    prep_kernel<<<(Nn * Mm / 4 + 255) / 256, 256>>>(out1, out2);
    fused_pass<<<4608, 256, SMEM_BYTES>>>(label);
    recip_kernel<<<32, 256>>>();
    pass3_corr<<<1024, 256>>>(label);
    final_kernel<<<1, 1>>>((float*)d_out);
}